// round 8
// baseline (speedup 1.0000x reference)
#include <cuda_runtime.h>
#include <math.h>
#include <stdint.h>

#define TX 160
#define TY 40
#define BB 16
#define HH 256
#define CC 512
#define INDIM 128
#define VV 30000
#define G4 1024      // 4*H
#define FF 896       // H + C + IN

#define NBLK 128
#define NTHR 320

// ---------------- device scratch (static, no allocs) ----------------
__device__ __align__(256) float g_pctx[TX * BB * CC];          // 5.24 MB
__device__ __align__(256) float g_gates[BB * G4];
__device__ __align__(256) float g_hq[BB * CC];
__device__ __align__(256) float g_acc[BB * TX];                // [b][x]
__device__ __align__(256) float g_sc[BB * TX];                 // [b][x]
__device__ __align__(256) float g_atted[BB * CC];
__device__ __align__(256) float g_ifoc[BB * G4];
__device__ __align__(256) float g_feats[TY * BB * FF];         // 2.29 MB
__device__ __align__(256) float g_logits[TY * BB * VV];        // 76.8 MB
__device__ __align__(256) float g_cost[TY * BB];
__device__ float g_cov_sum;
__device__ __align__(128) unsigned g_bar;

// ---------------- helpers ----------------
__device__ __forceinline__ float tanh_fast(float x) {
    float y;
    asm("tanh.approx.f32 %0, %1;" : "=f"(y) : "f"(x));
    return y;
}
__device__ __forceinline__ float sig_fast(float x) {
    return fmaf(tanh_fast(0.5f * x), 0.5f, 0.5f);
}
__device__ __forceinline__ float warp_sum(float s) {
#pragma unroll
    for (int o = 16; o > 0; o >>= 1) s += __shfl_xor_sync(0xffffffffu, s, o);
    return s;
}

// accumulate one 4-wide K chunk of weight row into all 16 batch accumulators
#define ACC_CHUNK(WPTR, XEXPR) { \
    float4 w = *(const float4*)(WPTR); \
    _Pragma("unroll") \
    for (int b = 0; b < 16; b++) { \
        float4 x = *(const float4*)(XEXPR); \
        acc[b] = fmaf(w.x, x.x, fmaf(w.y, x.y, fmaf(w.z, x.z, fmaf(w.w, x.w, acc[b])))); \
    } }

#define ALLRED16() { \
    _Pragma("unroll") \
    for (int o = 16; o > 0; o >>= 1) { \
        _Pragma("unroll") \
        for (int b = 0; b < 16; b++) acc[b] += __shfl_xor_sync(0xffffffffu, acc[b], o); \
    } }

// fast monotonic grid barrier
__device__ __forceinline__ void grid_sync(unsigned& epoch) {
    __syncthreads();
    if (threadIdx.x == 0) {
        epoch += gridDim.x;
        asm volatile("red.release.gpu.global.add.u32 [%0], 1;" :: "l"(&g_bar) : "memory");
        unsigned v;
        while (true) {
            asm volatile("ld.acquire.gpu.global.u32 %0, [%1];" : "=r"(v) : "l"(&g_bar) : "memory");
            if (v >= epoch) break;
            __nanosleep(32);
        }
    }
    __syncthreads();
}

// ---------------- init ----------------
__global__ void init_kernel(const float* __restrict__ cov0) {
    int tid = threadIdx.x;
    if (tid == 0) { g_bar = 0u; g_cov_sum = 0.f; }
    for (int i = tid; i < BB * TX; i += blockDim.x) { g_acc[i] = cov0[i]; }
}

// ---------------- 3xTF32 tensor-core GEMM: C = A @ B^T + bias ----------------
// A: [M,K] row-major (M%128==0, K%32==0), Bm: [N,K] row-major (N guarded).
// smem: [row][k] 128x32 tiles, swizzle word = row*32 + (k ^ ((row&7)<<2)).

__device__ __forceinline__ void split_tf32(float v, float& hi, float& lo) {
    uint32_t bh;
    asm("cvt.rna.tf32.f32 %0, %1;" : "=r"(bh) : "f"(v));
    float fh = __uint_as_float(bh);
    float r = v - fh;
    uint32_t bl;
    asm("cvt.rna.tf32.f32 %0, %1;" : "=r"(bl) : "f"(r));
    hi = fh;
    lo = __uint_as_float(bl);
}
__device__ __forceinline__ void split4(float4 v, float4& hi, float4& lo) {
    split_tf32(v.x, hi.x, lo.x);
    split_tf32(v.y, hi.y, lo.y);
    split_tf32(v.z, hi.z, lo.z);
    split_tf32(v.w, hi.w, lo.w);
}
__device__ __forceinline__ void mma_tf32(float* d, const uint32_t* a, const uint32_t* b) {
    asm volatile(
        "mma.sync.aligned.m16n8k8.row.col.f32.tf32.tf32.f32 "
        "{%0,%1,%2,%3}, {%4,%5,%6,%7}, {%8,%9}, {%0,%1,%2,%3};"
        : "+f"(d[0]), "+f"(d[1]), "+f"(d[2]), "+f"(d[3])
        : "r"(a[0]), "r"(a[1]), "r"(a[2]), "r"(a[3]), "r"(b[0]), "r"(b[1]));
}

__global__ __launch_bounds__(256, 1) void gemm_tf32_abT_bias(
    const float* __restrict__ A, const float* __restrict__ Bm,
    const float* __restrict__ bias, float* __restrict__ Cout,
    int M, int N, int K)
{
    extern __shared__ __align__(16) float sm[];
    float* sAb = sm;              // 4096 floats
    float* sAs = sm + 4096;
    float* sBb = sm + 8192;
    float* sBs = sm + 12288;

    const int tid = threadIdx.x;
    const int lane = tid & 31, wid = tid >> 5;
    const int g = lane >> 2, tig = lane & 3;
    const int wm = wid & 3, wn = wid >> 2;      // warp tile rows wm*32, cols wn*64
    const int m0 = blockIdx.x * 128, n0 = blockIdx.y * 128;

    float acc[2][8][4];
#pragma unroll
    for (int mt = 0; mt < 2; mt++)
#pragma unroll
        for (int nt = 0; nt < 8; nt++)
#pragma unroll
            for (int r = 0; r < 4; r++) acc[mt][nt][r] = 0.f;

    for (int k0 = 0; k0 < K; k0 += 32) {
        // stage + split tiles
#pragma unroll
        for (int i = 0; i < 4; i++) {
            int f = tid + i * 256;          // 0..1023
            int row = f >> 3, k4 = f & 7;
            int widx = row * 32 + ((k4 * 4) ^ ((row & 7) << 2));
            float4 v = *(const float4*)(A + (size_t)(m0 + row) * K + k0 + k4 * 4);
            float4 hb, lb;
            split4(v, hb, lb);
            *(float4*)&sAb[widx] = hb;
            *(float4*)&sAs[widx] = lb;
            int gn = n0 + row;
            float4 w = make_float4(0.f, 0.f, 0.f, 0.f);
            if (gn < N) w = *(const float4*)(Bm + (size_t)gn * K + k0 + k4 * 4);
            split4(w, hb, lb);
            *(float4*)&sBb[widx] = hb;
            *(float4*)&sBs[widx] = lb;
        }
        __syncthreads();
#pragma unroll
        for (int k8 = 0; k8 < 4; k8++) {
            const int kb = k8 * 8;
            uint32_t ab[2][4], as_[2][4];
#pragma unroll
            for (int mt = 0; mt < 2; mt++) {
                int r0 = wm * 32 + mt * 16 + g;     // r0&7 == g (since bases mult of 8... wm*32+mt*16 mult of 16)
                int sw = (r0 & 7) << 2;
                int i0 = r0 * 32 + ((kb + tig) ^ sw);
                int i1 = r0 * 32 + ((kb + tig + 4) ^ sw);
                ab[mt][0] = __float_as_uint(sAb[i0]);
                ab[mt][1] = __float_as_uint(sAb[i0 + 256]);   // row +8, same swizzle
                ab[mt][2] = __float_as_uint(sAb[i1]);
                ab[mt][3] = __float_as_uint(sAb[i1 + 256]);
                as_[mt][0] = __float_as_uint(sAs[i0]);
                as_[mt][1] = __float_as_uint(sAs[i0 + 256]);
                as_[mt][2] = __float_as_uint(sAs[i1]);
                as_[mt][3] = __float_as_uint(sAs[i1 + 256]);
            }
            uint32_t bb[8][2], bs[8][2];
#pragma unroll
            for (int nt = 0; nt < 8; nt++) {
                int c0 = wn * 64 + nt * 8 + g;
                int sw = (c0 & 7) << 2;
                int j0 = c0 * 32 + ((kb + tig) ^ sw);
                int j1 = c0 * 32 + ((kb + tig + 4) ^ sw);
                bb[nt][0] = __float_as_uint(sBb[j0]);
                bb[nt][1] = __float_as_uint(sBb[j1]);
                bs[nt][0] = __float_as_uint(sBs[j0]);
                bs[nt][1] = __float_as_uint(sBs[j1]);
            }
#pragma unroll
            for (int mt = 0; mt < 2; mt++)
#pragma unroll
                for (int nt = 0; nt < 8; nt++) {
                    mma_tf32(acc[mt][nt], ab[mt], bb[nt]);
                    mma_tf32(acc[mt][nt], ab[mt], bs[nt]);
                    mma_tf32(acc[mt][nt], as_[mt], bb[nt]);
                }
        }
        __syncthreads();
    }
    // epilogue
#pragma unroll
    for (int mt = 0; mt < 2; mt++) {
        int r0 = m0 + wm * 32 + mt * 16 + g;
#pragma unroll
        for (int nt = 0; nt < 8; nt++) {
            int c = n0 + wn * 64 + nt * 8 + tig * 2;
            if (c + 1 < N) {
                float2 v0 = make_float2(acc[mt][nt][0] + bias[c], acc[mt][nt][1] + bias[c + 1]);
                float2 v1 = make_float2(acc[mt][nt][2] + bias[c], acc[mt][nt][3] + bias[c + 1]);
                *(float2*)&Cout[(size_t)r0 * N + c] = v0;
                *(float2*)&Cout[(size_t)(r0 + 8) * N + c] = v1;
            } else if (c < N) {
                Cout[(size_t)r0 * N + c] = acc[mt][nt][0] + bias[c];
                Cout[(size_t)(r0 + 8) * N + c] = acc[mt][nt][2] + bias[c];
            }
        }
    }
}
#define GEMM_SMEM (16384 * 4)

// ---------------- persistent recurrence (unchanged from round 7) ----------------
#define OFF_H    0
#define OFF_C    4096
#define OFF_H1   8192
#define OFF_C1   12288
#define OFF_WATT 16384
#define OFF_ATTP 16544
#define OFF_WCOV 16864
#define OFF_UATT 17376
#define SMEM_FLOATS 17888
#define SMEM_BYTES (SMEM_FLOATS * 4)

__global__ __launch_bounds__(NTHR, 1) void decoder_kernel(
    const float* __restrict__ y_emb, const float* __restrict__ context,
    const float* __restrict__ x_mask, const float* __restrict__ y_mask,
    const float* __restrict__ h0, const float* __restrict__ c0,
    const float* __restrict__ W_ih, const float* __restrict__ W_hh,
    const float* __restrict__ b_ih, const float* __restrict__ b_hh,
    const float* __restrict__ Wx, const float* __restrict__ Ux, const float* __restrict__ bx,
    const float* __restrict__ W_comb, const float* __restrict__ U_att,
    const float* __restrict__ W_cov)
{
    extern __shared__ __align__(16) float sh[];
    float* sh_h    = sh + OFF_H;
    float* sh_c    = sh + OFF_C;
    float* sh_h1   = sh + OFF_H1;
    float* sh_c1   = sh + OFF_C1;
    float* sh_watt = sh + OFF_WATT;
    float* sh_attp = sh + OFF_ATTP;
    float* sh_wcov = sh + OFF_WCOV;
    float* sh_uatt = sh + OFF_UATT;

    const int tid = threadIdx.x;
    const int bk = blockIdx.x;
    const int lane = tid & 31;
    const int lwid = tid >> 5;
    const int myb = bk >> 3;
    const int sub = bk & 7;
    unsigned epoch = 0;

    for (int i = tid; i < BB * HH; i += NTHR) { sh_h[i] = h0[i]; sh_c[i] = c0[i]; }
    for (int i = tid; i < CC; i += NTHR) { sh_wcov[i] = W_cov[i]; sh_uatt[i] = U_att[i]; }
    __syncthreads();

    for (int t = 0; t < TY; t++) {
        const float* yrow = y_emb + (size_t)t * BB * INDIM;

        // P1
        if (lwid < 8) {
            int j = lwid * NBLK + bk;
            float acc[16];
#pragma unroll
            for (int b = 0; b < 16; b++) acc[b] = 0.f;
            ACC_CHUNK(W_ih + (size_t)j * INDIM + lane * 4,     yrow + b * INDIM + lane * 4);
            ACC_CHUNK(W_hh + (size_t)j * HH + lane * 4,        sh_h + b * HH + lane * 4);
            ACC_CHUNK(W_hh + (size_t)j * HH + 128 + lane * 4,  sh_h + b * HH + 128 + lane * 4);
            ALLRED16();
            float bias = b_ih[j] + b_hh[j];
#pragma unroll
            for (int b = 0; b < 16; b++)
                if (lane == b) g_gates[b * G4 + j] = acc[b] + bias;
        }
        grid_sync(epoch);

        // P2
        for (int idx = tid; idx < BB * HH; idx += NTHR) {
            int b = idx >> 8, u = idx & 255;
            const float* gb = g_gates + b * G4 + u;
            float gi = gb[0], gf = gb[HH], gg = gb[2 * HH], go = gb[3 * HH];
            float c_old = sh_c[idx], h_old = sh_h[idx];
            float c1 = sig_fast(gf) * c_old + sig_fast(gi) * tanh_fast(gg);
            float h1 = sig_fast(go) * tanh_fast(c1);
            float ym = y_mask[t * BB + b];
            sh_h1[idx] = ym * h1 + (1.f - ym) * h_old;
            sh_c1[idx] = ym * c1 + (1.f - ym) * c_old;
        }
        __syncthreads();

        // P3
        if (lwid < 4) {
            int o = lwid * NBLK + bk;
            const float* wr = W_comb + (size_t)o * (2 * HH);
            float acc[16];
#pragma unroll
            for (int b = 0; b < 16; b++) acc[b] = 0.f;
            ACC_CHUNK(wr + lane * 4,        sh_h1 + b * HH + lane * 4);
            ACC_CHUNK(wr + 128 + lane * 4,  sh_h1 + b * HH + 128 + lane * 4);
            ACC_CHUNK(wr + 256 + lane * 4,  sh_c1 + b * HH + lane * 4);
            ACC_CHUNK(wr + 384 + lane * 4,  sh_c1 + b * HH + 128 + lane * 4);
            ALLRED16();
#pragma unroll
            for (int b = 0; b < 16; b++)
                if (lane == b) g_hq[b * CC + o] = acc[b];
        }
        grid_sync(epoch);

        // P4
#pragma unroll
        for (int r = 0; r < 2; r++) {
            int p = (r * 10 + lwid) * NBLK + bk;
            int x = p >> 4, b = p & 15;
            float accv = g_acc[b * TX + x];
            const float* pc = g_pctx + (size_t)p * CC;
            const float* hqb = g_hq + b * CC;
            float s = 0.f;
#pragma unroll
            for (int i = 0; i < 16; i++) {
                int c = i * 32 + lane;
                s += tanh_fast(fmaf(accv, sh_wcov[c], pc[c] + hqb[c])) * sh_uatt[c];
            }
            s = warp_sum(s);
            if (lane == 0) g_sc[b * TX + x] = x_mask[p] * s;
        }
        grid_sync(epoch);

        // P5a
        if (lwid == 0) {
            float v[5];
            float mx = -3.4e38f;
#pragma unroll
            for (int i = 0; i < 5; i++) {
                v[i] = g_sc[myb * TX + i * 32 + lane];
                mx = fmaxf(mx, v[i]);
            }
#pragma unroll
            for (int o = 16; o > 0; o >>= 1) mx = fmaxf(mx, __shfl_xor_sync(0xffffffffu, mx, o));
            float sm = 0.f;
#pragma unroll
            for (int i = 0; i < 5; i++) {
                v[i] = __expf(v[i] - mx) * x_mask[(i * 32 + lane) * BB + myb];
                sm += v[i];
            }
            sm = warp_sum(sm);
            float inv = __fdividef(1.f, sm);
#pragma unroll
            for (int i = 0; i < 5; i++) sh_watt[i * 32 + lane] = v[i] * inv;
        }
        __syncthreads();

        // P5b
        {
            int jid = sub * 10 + lwid;
            int cck = jid / 5, xck = jid % 5;
            int c = cck * 32 + lane;
            float s = 0.f;
#pragma unroll 8
            for (int i = 0; i < 32; i++) {
                int x = xck * 32 + i;
                s = fmaf(sh_watt[x], context[(size_t)(x * BB + myb) * CC + c], s);
            }
            sh_attp[(cck & 1) * 160 + xck * 32 + lane] = s;
        }
        __syncthreads();
        if (tid < 64) {
            int lc = tid >> 5, cl = tid & 31;
            const float* ap = sh_attp + lc * 160 + cl;
            float s = ap[0] + ap[32] + ap[64] + ap[96] + ap[128];
            g_atted[myb * CC + (2 * sub + lc) * 32 + cl] = s;
        }
        if (sub == 0 && lwid == 2) {
            float part = 0.f;
#pragma unroll
            for (int i = 0; i < 5; i++) {
                int x = i * 32 + lane;
                float w = sh_watt[x];
                float old = g_acc[myb * TX + x];
                part += fminf(w, old);
                g_acc[myb * TX + x] = old + w;
            }
            part = warp_sum(part);
            if (lane == 0) atomicAdd(&g_cov_sum, part);
        }
        grid_sync(epoch);

        // P6
        if (lwid < 8) {
            int j = lwid * NBLK + bk;
            float acc[16];
#pragma unroll
            for (int b = 0; b < 16; b++) acc[b] = 0.f;
            ACC_CHUNK(Ux + (size_t)j * HH + lane * 4,        sh_h1 + b * HH + lane * 4);
            ACC_CHUNK(Ux + (size_t)j * HH + 128 + lane * 4,  sh_h1 + b * HH + 128 + lane * 4);
#pragma unroll
            for (int cc = 0; cc < 4; cc++) {
                ACC_CHUNK(Wx + (size_t)j * CC + cc * 128 + lane * 4,
                          g_atted + b * CC + cc * 128 + lane * 4);
            }
            ALLRED16();
            float bias = bx[j];
#pragma unroll
            for (int b = 0; b < 16; b++)
                if (lane == b) g_ifoc[b * G4 + j] = acc[b] + bias;
        }
        grid_sync(epoch);

        // P7
        for (int idx = tid; idx < BB * HH; idx += NTHR) {
            int b = idx >> 8, u = idx & 255;
            const float* fb = g_ifoc + b * G4 + u;
            float i2 = fb[0], f2 = fb[HH], o2 = fb[2 * HH], g2 = fb[3 * HH];
            float c1 = sh_c1[idx], h1 = sh_h1[idx];
            float c2 = sig_fast(f2) * c1 + sig_fast(i2) * tanh_fast(g2);
            float h2 = sig_fast(o2) * tanh_fast(c2);
            float ym = y_mask[t * BB + b];
            c2 = ym * c2 + (1.f - ym) * c1;
            h2 = ym * h2 + (1.f - ym) * h1;
            sh_h[idx] = h2;
            sh_c[idx] = c2;
            g_feats[(size_t)(t * BB + b) * FF + u] = h2;
        }
        for (int idx2 = bk * NTHR + tid; idx2 < BB * (CC + INDIM); idx2 += NBLK * NTHR) {
            if (idx2 < BB * CC) {
                int b = idx2 >> 9, c = idx2 & 511;
                g_feats[(size_t)(t * BB + b) * FF + HH + c] = g_atted[idx2];
            } else {
                int q = idx2 - BB * CC;
                int b = q >> 7, kk = q & 127;
                g_feats[(size_t)(t * BB + b) * FF + HH + CC + kk] = yrow[b * INDIM + kk];
            }
        }
        __syncthreads();
    }
}

// ---------------- online softmax / cost per row ----------------
__global__ __launch_bounds__(256) void softmax_cost_kernel(const int* __restrict__ y_idx,
                                                           float* __restrict__ out) {
    __shared__ float smx[256], ssm[256];
    const int m = blockIdx.x;
    const int tid = threadIdx.x;
    const float* row = g_logits + (size_t)m * VV;

    float mx = -3.4e38f, sm = 0.f;
    for (int v = tid; v < VV; v += 256) {
        float x = row[v];
        float nm = fmaxf(mx, x);
        sm = sm * __expf(mx - nm) + __expf(x - nm);
        mx = nm;
    }
    smx[tid] = mx; ssm[tid] = sm; __syncthreads();
    for (int s = 128; s > 0; s >>= 1) {
        if (tid < s) {
            float m2 = smx[tid + s], s2 = ssm[tid + s];
            float nm = fmaxf(smx[tid], m2);
            ssm[tid] = ssm[tid] * __expf(smx[tid] - nm) + s2 * __expf(m2 - nm);
            smx[tid] = nm;
        }
        __syncthreads();
    }
    float M = smx[0], S = ssm[0];
    if (tid == 0) g_cost[m] = M + logf(S) - row[y_idx[m]];

    if (m >= (TY - 1) * BB) {
        int b = m - (TY - 1) * BB;
        float inv = __fdividef(1.f, S);
        for (int v = tid; v < VV; v += 256)
            out[(size_t)b * VV + v] = __expf(row[v] - M) * inv;
    }
}

// ---------------- final scalars ----------------
__global__ void finalize_kernel(const float* __restrict__ y_mask, float* __restrict__ out) {
    int b = threadIdx.x;
    float cb = 0.f;
    if (b < BB) {
        float num = 0.f, den = 0.f;
        for (int t = 0; t < TY; t++) {
            float ym = y_mask[t * BB + b];
            num += g_cost[t * BB + b] * ym;
            den += ym;
        }
        cb = num / den;
    }
#pragma unroll
    for (int o = 16; o > 0; o >>= 1) cb += __shfl_xor_sync(0xffffffffu, cb, o);
    if (threadIdx.x == 0) {
        out[(size_t)BB * VV]     = cb / (float)BB;
        out[(size_t)BB * VV + 1] = g_cov_sum / (float)(TY * BB);
    }
}

// ---------------- launch ----------------
extern "C" void kernel_launch(void* const* d_in, const int* in_sizes, int n_in,
                              void* d_out, int out_size) {
    const float* y_emb   = (const float*)d_in[0];
    const float* context = (const float*)d_in[1];
    const float* h0      = (const float*)d_in[2];
    const float* c0      = (const float*)d_in[3];
    const float* x_mask  = (const float*)d_in[4];
    const float* y_mask  = (const float*)d_in[5];
    const float* cov0    = (const float*)d_in[6];
    const int*   y_idx   = (const int*)d_in[7];
    const float* W_ih    = (const float*)d_in[8];
    const float* W_hh    = (const float*)d_in[9];
    const float* b_ih    = (const float*)d_in[10];
    const float* b_hh    = (const float*)d_in[11];
    const float* Wx      = (const float*)d_in[12];
    const float* Ux      = (const float*)d_in[13];
    const float* bx      = (const float*)d_in[14];
    const float* Wc_att  = (const float*)d_in[15];
    const float* b_att   = (const float*)d_in[16];
    const float* W_comb  = (const float*)d_in[17];
    const float* U_att   = (const float*)d_in[18];
    const float* W_cov   = (const float*)d_in[19];
    const float* Wp      = (const float*)d_in[20];
    const float* bp      = (const float*)d_in[21];
    float* out = (float*)d_out;

    void *p_pctx, *p_feats, *p_logits;
    cudaGetSymbolAddress(&p_pctx, g_pctx);
    cudaGetSymbolAddress(&p_feats, g_feats);
    cudaGetSymbolAddress(&p_logits, g_logits);

    cudaFuncSetAttribute(decoder_kernel,
                         cudaFuncAttributeMaxDynamicSharedMemorySize, SMEM_BYTES);
    cudaFuncSetAttribute(gemm_tf32_abT_bias,
                         cudaFuncAttributeMaxDynamicSharedMemorySize, GEMM_SMEM);

    init_kernel<<<1, 256>>>(cov0);

    // pctx = context @ Wc_att^T + b_att : M=2560, N=512, K=512
    {
        dim3 grid((TX * BB) / 128, CC / 128);   // (20, 4)
        gemm_tf32_abT_bias<<<grid, 256, GEMM_SMEM>>>(context, Wc_att, b_att,
                                                     (float*)p_pctx, TX * BB, CC, CC);
    }

    decoder_kernel<<<NBLK, NTHR, SMEM_BYTES>>>(y_emb, context, x_mask, y_mask,
                                               h0, c0,
                                               W_ih, W_hh, b_ih, b_hh, Wx, Ux, bx,
                                               W_comb, U_att, W_cov);

    // logits = feats @ Wp^T + bp : M=640, N=30000, K=896
    {
        dim3 grid((TY * BB) / 128, (VV + 127) / 128);   // (5, 235)
        gemm_tf32_abT_bias<<<grid, 256, GEMM_SMEM>>>((const float*)p_feats, Wp, bp,
                                                     (float*)p_logits, TY * BB, VV, FF);
    }

    softmax_cost_kernel<<<TY * BB, 256>>>(y_idx, out);
    finalize_kernel<<<1, 32>>>(y_mask, out);
}

// round 9
// speedup vs baseline: 1.0727x; 1.0727x over previous
#include <cuda_runtime.h>
#include <math.h>
#include <stdint.h>

#define TX 160
#define TY 40
#define BB 16
#define HH 256
#define CC 512
#define INDIM 128
#define VV 30000
#define G4 1024      // 4*H
#define FF 896       // H + C + IN

#define NBLK 128
#define NTHR 320

// ---------------- device scratch (static, no allocs) ----------------
__device__ __align__(256) float g_pctx[TX * BB * CC];          // 5.24 MB
__device__ __align__(256) float g_gates[BB * G4];
__device__ __align__(256) float g_hq[BB * CC];
__device__ __align__(256) float g_acc[BB * TX];                // [b][x]
__device__ __align__(256) float g_sc[BB * TX];                 // [b][x]
__device__ __align__(256) float g_atted[BB * CC];
__device__ __align__(256) float g_ifoc[BB * G4];
__device__ __align__(256) float g_feats[TY * BB * FF];         // 2.29 MB
__device__ __align__(256) float g_logits[TY * BB * VV];        // 76.8 MB
__device__ __align__(256) float g_cost[TY * BB];
__device__ float g_cov_sum;
__device__ __align__(128) unsigned g_bar;

// ---------------- helpers ----------------
__device__ __forceinline__ float tanh_fast(float x) {
    float y;
    asm("tanh.approx.f32 %0, %1;" : "=f"(y) : "f"(x));
    return y;
}
__device__ __forceinline__ float sig_fast(float x) {
    return fmaf(tanh_fast(0.5f * x), 0.5f, 0.5f);
}
__device__ __forceinline__ float warp_sum(float s) {
#pragma unroll
    for (int o = 16; o > 0; o >>= 1) s += __shfl_xor_sync(0xffffffffu, s, o);
    return s;
}

#define ACC_CHUNK(WPTR, XEXPR) { \
    float4 w = *(const float4*)(WPTR); \
    _Pragma("unroll") \
    for (int b = 0; b < 16; b++) { \
        float4 x = *(const float4*)(XEXPR); \
        acc[b] = fmaf(w.x, x.x, fmaf(w.y, x.y, fmaf(w.z, x.z, fmaf(w.w, x.w, acc[b])))); \
    } }

#define ALLRED16() { \
    _Pragma("unroll") \
    for (int o = 16; o > 0; o >>= 1) { \
        _Pragma("unroll") \
        for (int b = 0; b < 16; b++) acc[b] += __shfl_xor_sync(0xffffffffu, acc[b], o); \
    } }

// fast monotonic grid barrier
__device__ __forceinline__ void grid_sync(unsigned& epoch) {
    __syncthreads();
    if (threadIdx.x == 0) {
        epoch += gridDim.x;
        asm volatile("red.release.gpu.global.add.u32 [%0], 1;" :: "l"(&g_bar) : "memory");
        unsigned v;
        while (true) {
            asm volatile("ld.acquire.gpu.global.u32 %0, [%1];" : "=r"(v) : "l"(&g_bar) : "memory");
            if (v >= epoch) break;
            __nanosleep(32);
        }
    }
    __syncthreads();
}

// ---------------- init ----------------
__global__ void init_kernel(const float* __restrict__ cov0) {
    int tid = threadIdx.x;
    if (tid == 0) { g_bar = 0u; g_cov_sum = 0.f; }
    for (int i = tid; i < BB * TX; i += blockDim.x) { g_acc[i] = cov0[i]; }
}

// ---------------- 3xTF32 tensor-core GEMM, double-buffered pipeline ----------------
__device__ __forceinline__ void split_tf32(float v, float& hi, float& lo) {
    uint32_t bh;
    asm("cvt.rna.tf32.f32 %0, %1;" : "=r"(bh) : "f"(v));
    float fh = __uint_as_float(bh);
    float r = v - fh;
    uint32_t bl;
    asm("cvt.rna.tf32.f32 %0, %1;" : "=r"(bl) : "f"(r));
    hi = fh;
    lo = __uint_as_float(bl);
}
__device__ __forceinline__ void split4(float4 v, float4& hi, float4& lo) {
    split_tf32(v.x, hi.x, lo.x);
    split_tf32(v.y, hi.y, lo.y);
    split_tf32(v.z, hi.z, lo.z);
    split_tf32(v.w, hi.w, lo.w);
}
__device__ __forceinline__ void mma_tf32(float* d, const uint32_t* a, const uint32_t* b) {
    asm volatile(
        "mma.sync.aligned.m16n8k8.row.col.f32.tf32.tf32.f32 "
        "{%0,%1,%2,%3}, {%4,%5,%6,%7}, {%8,%9}, {%0,%1,%2,%3};"
        : "+f"(d[0]), "+f"(d[1]), "+f"(d[2]), "+f"(d[3])
        : "r"(a[0]), "r"(a[1]), "r"(a[2]), "r"(a[3]), "r"(b[0]), "r"(b[1]));
}

// per-stage layout (floats): sAb 4096 | sAs 4096 | sBb 4096 | sBs 4096
#define STG 16384
#define GEMM_SMEM (2 * STG * 4)

__global__ __launch_bounds__(256, 1) void gemm_tf32_abT_bias(
    const float* __restrict__ A, const float* __restrict__ Bm,
    const float* __restrict__ bias, float* __restrict__ Cout,
    int M, int N, int K)
{
    extern __shared__ __align__(16) float sm[];

    const int tid = threadIdx.x;
    const int lane = tid & 31, wid = tid >> 5;
    const int g = lane >> 2, tig = lane & 3;
    const int wm = wid & 3, wn = wid >> 2;
    const int m0 = blockIdx.x * 128, n0 = blockIdx.y * 128;
    const int nt = K >> 5;                   // K % 32 == 0

    // staging address components (same for every tile)
    const int s_row[4] = { (tid + 0) >> 3, (tid + 256) >> 3, (tid + 512) >> 3, (tid + 768) >> 3 };
    const int s_k4 = tid & 7;

    float acc[2][8][4];
#pragma unroll
    for (int mt = 0; mt < 2; mt++)
#pragma unroll
        for (int ntt = 0; ntt < 8; ntt++)
#pragma unroll
            for (int r = 0; r < 4; r++) acc[mt][ntt][r] = 0.f;

    float4 ra[4], rb[4];

#define LDG_TILE(KT) { \
    int k0 = (KT) * 32; \
    _Pragma("unroll") \
    for (int i = 0; i < 4; i++) { \
        ra[i] = *(const float4*)(A + (size_t)(m0 + s_row[i]) * K + k0 + s_k4 * 4); \
        int gn = n0 + s_row[i]; \
        rb[i] = make_float4(0.f, 0.f, 0.f, 0.f); \
        if (gn < N) rb[i] = *(const float4*)(Bm + (size_t)gn * K + k0 + s_k4 * 4); \
    } }

#define STS_TILE(ST) { \
    float* base = sm + (ST) * STG; \
    _Pragma("unroll") \
    for (int i = 0; i < 4; i++) { \
        int widx = s_row[i] * 32 + ((s_k4 * 4) ^ ((s_row[i] & 7) << 2)); \
        float4 hb, lb; \
        split4(ra[i], hb, lb); \
        *(float4*)&base[widx] = hb; \
        *(float4*)&base[4096 + widx] = lb; \
        split4(rb[i], hb, lb); \
        *(float4*)&base[8192 + widx] = hb; \
        *(float4*)&base[12288 + widx] = lb; \
    } }

    // prologue
    LDG_TILE(0);
    STS_TILE(0);
    if (nt > 1) LDG_TILE(1);
    __syncthreads();

    for (int kt = 0; kt < nt; kt++) {
        const float* sAb = sm + (kt & 1) * STG;
        const float* sAs = sAb + 4096;
        const float* sBb = sAb + 8192;
        const float* sBs = sAb + 12288;
#pragma unroll
        for (int k8 = 0; k8 < 4; k8++) {
            const int kb = k8 * 8;
            uint32_t ab[2][4], as_[2][4];
#pragma unroll
            for (int mt = 0; mt < 2; mt++) {
                int r0 = wm * 32 + mt * 16 + g;
                int sw = (r0 & 7) << 2;
                int i0 = r0 * 32 + ((kb + tig) ^ sw);
                int i1 = r0 * 32 + ((kb + tig + 4) ^ sw);
                ab[mt][0] = __float_as_uint(sAb[i0]);
                ab[mt][1] = __float_as_uint(sAb[i0 + 256]);
                ab[mt][2] = __float_as_uint(sAb[i1]);
                ab[mt][3] = __float_as_uint(sAb[i1 + 256]);
                as_[mt][0] = __float_as_uint(sAs[i0]);
                as_[mt][1] = __float_as_uint(sAs[i0 + 256]);
                as_[mt][2] = __float_as_uint(sAs[i1]);
                as_[mt][3] = __float_as_uint(sAs[i1 + 256]);
            }
            uint32_t bb[8][2], bs[8][2];
#pragma unroll
            for (int ntt = 0; ntt < 8; ntt++) {
                int c0 = wn * 64 + ntt * 8 + g;
                int sw = (c0 & 7) << 2;
                int j0 = c0 * 32 + ((kb + tig) ^ sw);
                int j1 = c0 * 32 + ((kb + tig + 4) ^ sw);
                bb[ntt][0] = __float_as_uint(sBb[j0]);
                bb[ntt][1] = __float_as_uint(sBb[j1]);
                bs[ntt][0] = __float_as_uint(sBs[j0]);
                bs[ntt][1] = __float_as_uint(sBs[j1]);
            }
#pragma unroll
            for (int mt = 0; mt < 2; mt++)
#pragma unroll
                for (int ntt = 0; ntt < 8; ntt++) {
                    mma_tf32(acc[mt][ntt], ab[mt], bb[ntt]);
                    mma_tf32(acc[mt][ntt], ab[mt], bs[ntt]);
                    mma_tf32(acc[mt][ntt], as_[mt], bb[ntt]);
                }
        }
        if (kt + 1 < nt) {
            // stage (kt+1)&1 was last read two iterations ago; the sync at the
            // end of the previous iteration orders all those reads before us.
            STS_TILE((kt + 1) & 1);
            if (kt + 2 < nt) LDG_TILE(kt + 2);
            __syncthreads();
        }
    }

    // epilogue
#pragma unroll
    for (int mt = 0; mt < 2; mt++) {
        int r0 = m0 + wm * 32 + mt * 16 + g;
#pragma unroll
        for (int ntt = 0; ntt < 8; ntt++) {
            int c = n0 + wn * 64 + ntt * 8 + tig * 2;
            if (c + 1 < N) {
                float2 v0 = make_float2(acc[mt][ntt][0] + bias[c], acc[mt][ntt][1] + bias[c + 1]);
                float2 v1 = make_float2(acc[mt][ntt][2] + bias[c], acc[mt][ntt][3] + bias[c + 1]);
                *(float2*)&Cout[(size_t)r0 * N + c] = v0;
                *(float2*)&Cout[(size_t)(r0 + 8) * N + c] = v1;
            } else if (c < N) {
                Cout[(size_t)r0 * N + c] = acc[mt][ntt][0] + bias[c];
                Cout[(size_t)(r0 + 8) * N + c] = acc[mt][ntt][2] + bias[c];
            }
        }
    }
#undef LDG_TILE
#undef STS_TILE
}

// ---------------- persistent recurrence (unchanged) ----------------
#define OFF_H    0
#define OFF_C    4096
#define OFF_H1   8192
#define OFF_C1   12288
#define OFF_WATT 16384
#define OFF_ATTP 16544
#define OFF_WCOV 16864
#define OFF_UATT 17376
#define SMEM_FLOATS 17888
#define SMEM_BYTES (SMEM_FLOATS * 4)

__global__ __launch_bounds__(NTHR, 1) void decoder_kernel(
    const float* __restrict__ y_emb, const float* __restrict__ context,
    const float* __restrict__ x_mask, const float* __restrict__ y_mask,
    const float* __restrict__ h0, const float* __restrict__ c0,
    const float* __restrict__ W_ih, const float* __restrict__ W_hh,
    const float* __restrict__ b_ih, const float* __restrict__ b_hh,
    const float* __restrict__ Wx, const float* __restrict__ Ux, const float* __restrict__ bx,
    const float* __restrict__ W_comb, const float* __restrict__ U_att,
    const float* __restrict__ W_cov)
{
    extern __shared__ __align__(16) float sh[];
    float* sh_h    = sh + OFF_H;
    float* sh_c    = sh + OFF_C;
    float* sh_h1   = sh + OFF_H1;
    float* sh_c1   = sh + OFF_C1;
    float* sh_watt = sh + OFF_WATT;
    float* sh_attp = sh + OFF_ATTP;
    float* sh_wcov = sh + OFF_WCOV;
    float* sh_uatt = sh + OFF_UATT;

    const int tid = threadIdx.x;
    const int bk = blockIdx.x;
    const int lane = tid & 31;
    const int lwid = tid >> 5;
    const int myb = bk >> 3;
    const int sub = bk & 7;
    unsigned epoch = 0;

    for (int i = tid; i < BB * HH; i += NTHR) { sh_h[i] = h0[i]; sh_c[i] = c0[i]; }
    for (int i = tid; i < CC; i += NTHR) { sh_wcov[i] = W_cov[i]; sh_uatt[i] = U_att[i]; }
    __syncthreads();

    for (int t = 0; t < TY; t++) {
        const float* yrow = y_emb + (size_t)t * BB * INDIM;

        // P1
        if (lwid < 8) {
            int j = lwid * NBLK + bk;
            float acc[16];
#pragma unroll
            for (int b = 0; b < 16; b++) acc[b] = 0.f;
            ACC_CHUNK(W_ih + (size_t)j * INDIM + lane * 4,     yrow + b * INDIM + lane * 4);
            ACC_CHUNK(W_hh + (size_t)j * HH + lane * 4,        sh_h + b * HH + lane * 4);
            ACC_CHUNK(W_hh + (size_t)j * HH + 128 + lane * 4,  sh_h + b * HH + 128 + lane * 4);
            ALLRED16();
            float bias = b_ih[j] + b_hh[j];
#pragma unroll
            for (int b = 0; b < 16; b++)
                if (lane == b) g_gates[b * G4 + j] = acc[b] + bias;
        }
        grid_sync(epoch);

        // P2
        for (int idx = tid; idx < BB * HH; idx += NTHR) {
            int b = idx >> 8, u = idx & 255;
            const float* gb = g_gates + b * G4 + u;
            float gi = gb[0], gf = gb[HH], gg = gb[2 * HH], go = gb[3 * HH];
            float c_old = sh_c[idx], h_old = sh_h[idx];
            float c1 = sig_fast(gf) * c_old + sig_fast(gi) * tanh_fast(gg);
            float h1 = sig_fast(go) * tanh_fast(c1);
            float ym = y_mask[t * BB + b];
            sh_h1[idx] = ym * h1 + (1.f - ym) * h_old;
            sh_c1[idx] = ym * c1 + (1.f - ym) * c_old;
        }
        __syncthreads();

        // P3
        if (lwid < 4) {
            int o = lwid * NBLK + bk;
            const float* wr = W_comb + (size_t)o * (2 * HH);
            float acc[16];
#pragma unroll
            for (int b = 0; b < 16; b++) acc[b] = 0.f;
            ACC_CHUNK(wr + lane * 4,        sh_h1 + b * HH + lane * 4);
            ACC_CHUNK(wr + 128 + lane * 4,  sh_h1 + b * HH + 128 + lane * 4);
            ACC_CHUNK(wr + 256 + lane * 4,  sh_c1 + b * HH + lane * 4);
            ACC_CHUNK(wr + 384 + lane * 4,  sh_c1 + b * HH + 128 + lane * 4);
            ALLRED16();
#pragma unroll
            for (int b = 0; b < 16; b++)
                if (lane == b) g_hq[b * CC + o] = acc[b];
        }
        grid_sync(epoch);

        // P4
#pragma unroll
        for (int r = 0; r < 2; r++) {
            int p = (r * 10 + lwid) * NBLK + bk;
            int x = p >> 4, b = p & 15;
            float accv = g_acc[b * TX + x];
            const float* pc = g_pctx + (size_t)p * CC;
            const float* hqb = g_hq + b * CC;
            float s = 0.f;
#pragma unroll
            for (int i = 0; i < 16; i++) {
                int c = i * 32 + lane;
                s += tanh_fast(fmaf(accv, sh_wcov[c], pc[c] + hqb[c])) * sh_uatt[c];
            }
            s = warp_sum(s);
            if (lane == 0) g_sc[b * TX + x] = x_mask[p] * s;
        }
        grid_sync(epoch);

        // P5a
        if (lwid == 0) {
            float v[5];
            float mx = -3.4e38f;
#pragma unroll
            for (int i = 0; i < 5; i++) {
                v[i] = g_sc[myb * TX + i * 32 + lane];
                mx = fmaxf(mx, v[i]);
            }
#pragma unroll
            for (int o = 16; o > 0; o >>= 1) mx = fmaxf(mx, __shfl_xor_sync(0xffffffffu, mx, o));
            float sm = 0.f;
#pragma unroll
            for (int i = 0; i < 5; i++) {
                v[i] = __expf(v[i] - mx) * x_mask[(i * 32 + lane) * BB + myb];
                sm += v[i];
            }
            sm = warp_sum(sm);
            float inv = __fdividef(1.f, sm);
#pragma unroll
            for (int i = 0; i < 5; i++) sh_watt[i * 32 + lane] = v[i] * inv;
        }
        __syncthreads();

        // P5b
        {
            int jid = sub * 10 + lwid;
            int cck = jid / 5, xck = jid % 5;
            int c = cck * 32 + lane;
            float s = 0.f;
#pragma unroll 8
            for (int i = 0; i < 32; i++) {
                int x = xck * 32 + i;
                s = fmaf(sh_watt[x], context[(size_t)(x * BB + myb) * CC + c], s);
            }
            sh_attp[(cck & 1) * 160 + xck * 32 + lane] = s;
        }
        __syncthreads();
        if (tid < 64) {
            int lc = tid >> 5, cl = tid & 31;
            const float* ap = sh_attp + lc * 160 + cl;
            float s = ap[0] + ap[32] + ap[64] + ap[96] + ap[128];
            g_atted[myb * CC + (2 * sub + lc) * 32 + cl] = s;
        }
        if (sub == 0 && lwid == 2) {
            float part = 0.f;
#pragma unroll
            for (int i = 0; i < 5; i++) {
                int x = i * 32 + lane;
                float w = sh_watt[x];
                float old = g_acc[myb * TX + x];
                part += fminf(w, old);
                g_acc[myb * TX + x] = old + w;
            }
            part = warp_sum(part);
            if (lane == 0) atomicAdd(&g_cov_sum, part);
        }
        grid_sync(epoch);

        // P6
        if (lwid < 8) {
            int j = lwid * NBLK + bk;
            float acc[16];
#pragma unroll
            for (int b = 0; b < 16; b++) acc[b] = 0.f;
            ACC_CHUNK(Ux + (size_t)j * HH + lane * 4,        sh_h1 + b * HH + lane * 4);
            ACC_CHUNK(Ux + (size_t)j * HH + 128 + lane * 4,  sh_h1 + b * HH + 128 + lane * 4);
#pragma unroll
            for (int cc = 0; cc < 4; cc++) {
                ACC_CHUNK(Wx + (size_t)j * CC + cc * 128 + lane * 4,
                          g_atted + b * CC + cc * 128 + lane * 4);
            }
            ALLRED16();
            float bias = bx[j];
#pragma unroll
            for (int b = 0; b < 16; b++)
                if (lane == b) g_ifoc[b * G4 + j] = acc[b] + bias;
        }
        grid_sync(epoch);

        // P7
        for (int idx = tid; idx < BB * HH; idx += NTHR) {
            int b = idx >> 8, u = idx & 255;
            const float* fb = g_ifoc + b * G4 + u;
            float i2 = fb[0], f2 = fb[HH], o2 = fb[2 * HH], g2 = fb[3 * HH];
            float c1 = sh_c1[idx], h1 = sh_h1[idx];
            float c2 = sig_fast(f2) * c1 + sig_fast(i2) * tanh_fast(g2);
            float h2 = sig_fast(o2) * tanh_fast(c2);
            float ym = y_mask[t * BB + b];
            c2 = ym * c2 + (1.f - ym) * c1;
            h2 = ym * h2 + (1.f - ym) * h1;
            sh_h[idx] = h2;
            sh_c[idx] = c2;
            g_feats[(size_t)(t * BB + b) * FF + u] = h2;
        }
        for (int idx2 = bk * NTHR + tid; idx2 < BB * (CC + INDIM); idx2 += NBLK * NTHR) {
            if (idx2 < BB * CC) {
                int b = idx2 >> 9, c = idx2 & 511;
                g_feats[(size_t)(t * BB + b) * FF + HH + c] = g_atted[idx2];
            } else {
                int q = idx2 - BB * CC;
                int b = q >> 7, kk = q & 127;
                g_feats[(size_t)(t * BB + b) * FF + HH + CC + kk] = yrow[b * INDIM + kk];
            }
        }
        __syncthreads();
    }
}

// ---------------- online softmax / cost per row ----------------
__global__ __launch_bounds__(256) void softmax_cost_kernel(const int* __restrict__ y_idx,
                                                           float* __restrict__ out) {
    __shared__ float smx[256], ssm[256];
    const int m = blockIdx.x;
    const int tid = threadIdx.x;
    const float* row = g_logits + (size_t)m * VV;

    float mx = -3.4e38f, sm = 0.f;
    for (int v = tid; v < VV; v += 256) {
        float x = row[v];
        float nm = fmaxf(mx, x);
        sm = sm * __expf(mx - nm) + __expf(x - nm);
        mx = nm;
    }
    smx[tid] = mx; ssm[tid] = sm; __syncthreads();
    for (int s = 128; s > 0; s >>= 1) {
        if (tid < s) {
            float m2 = smx[tid + s], s2 = ssm[tid + s];
            float nm = fmaxf(smx[tid], m2);
            ssm[tid] = ssm[tid] * __expf(smx[tid] - nm) + s2 * __expf(m2 - nm);
            smx[tid] = nm;
        }
        __syncthreads();
    }
    float M = smx[0], S = ssm[0];
    if (tid == 0) g_cost[m] = M + logf(S) - row[y_idx[m]];

    if (m >= (TY - 1) * BB) {
        int b = m - (TY - 1) * BB;
        float inv = __fdividef(1.f, S);
        for (int v = tid; v < VV; v += 256)
            out[(size_t)b * VV + v] = __expf(row[v] - M) * inv;
    }
}

// ---------------- final scalars ----------------
__global__ void finalize_kernel(const float* __restrict__ y_mask, float* __restrict__ out) {
    int b = threadIdx.x;
    float cb = 0.f;
    if (b < BB) {
        float num = 0.f, den = 0.f;
        for (int t = 0; t < TY; t++) {
            float ym = y_mask[t * BB + b];
            num += g_cost[t * BB + b] * ym;
            den += ym;
        }
        cb = num / den;
    }
#pragma unroll
    for (int o = 16; o > 0; o >>= 1) cb += __shfl_xor_sync(0xffffffffu, cb, o);
    if (threadIdx.x == 0) {
        out[(size_t)BB * VV]     = cb / (float)BB;
        out[(size_t)BB * VV + 1] = g_cov_sum / (float)(TY * BB);
    }
}

// ---------------- launch ----------------
extern "C" void kernel_launch(void* const* d_in, const int* in_sizes, int n_in,
                              void* d_out, int out_size) {
    const float* y_emb   = (const float*)d_in[0];
    const float* context = (const float*)d_in[1];
    const float* h0      = (const float*)d_in[2];
    const float* c0      = (const float*)d_in[3];
    const float* x_mask  = (const float*)d_in[4];
    const float* y_mask  = (const float*)d_in[5];
    const float* cov0    = (const float*)d_in[6];
    const int*   y_idx   = (const int*)d_in[7];
    const float* W_ih    = (const float*)d_in[8];
    const float* W_hh    = (const float*)d_in[9];
    const float* b_ih    = (const float*)d_in[10];
    const float* b_hh    = (const float*)d_in[11];
    const float* Wx      = (const float*)d_in[12];
    const float* Ux      = (const float*)d_in[13];
    const float* bx      = (const float*)d_in[14];
    const float* Wc_att  = (const float*)d_in[15];
    const float* b_att   = (const float*)d_in[16];
    const float* W_comb  = (const float*)d_in[17];
    const float* U_att   = (const float*)d_in[18];
    const float* W_cov   = (const float*)d_in[19];
    const float* Wp      = (const float*)d_in[20];
    const float* bp      = (const float*)d_in[21];
    float* out = (float*)d_out;

    void *p_pctx, *p_feats, *p_logits;
    cudaGetSymbolAddress(&p_pctx, g_pctx);
    cudaGetSymbolAddress(&p_feats, g_feats);
    cudaGetSymbolAddress(&p_logits, g_logits);

    cudaFuncSetAttribute(decoder_kernel,
                         cudaFuncAttributeMaxDynamicSharedMemorySize, SMEM_BYTES);
    cudaFuncSetAttribute(gemm_tf32_abT_bias,
                         cudaFuncAttributeMaxDynamicSharedMemorySize, GEMM_SMEM);

    init_kernel<<<1, 256>>>(cov0);

    // pctx = context @ Wc_att^T + b_att : M=2560, N=512, K=512
    {
        dim3 grid((TX * BB) / 128, CC / 128);   // (20, 4)
        gemm_tf32_abT_bias<<<grid, 256, GEMM_SMEM>>>(context, Wc_att, b_att,
                                                     (float*)p_pctx, TX * BB, CC, CC);
    }

    decoder_kernel<<<NBLK, NTHR, SMEM_BYTES>>>(y_emb, context, x_mask, y_mask,
                                               h0, c0,
                                               W_ih, W_hh, b_ih, b_hh, Wx, Ux, bx,
                                               W_comb, U_att, W_cov);

    // logits = feats @ Wp^T + bp : M=640, N=30000, K=896
    {
        dim3 grid((TY * BB) / 128, (VV + 127) / 128);   // (5, 235)
        gemm_tf32_abT_bias<<<grid, 256, GEMM_SMEM>>>((const float*)p_feats, Wp, bp,
                                                     (float*)p_logits, TY * BB, VV, FF);
    }

    softmax_cost_kernel<<<TY * BB, 256>>>(y_idx, out);
    finalize_kernel<<<1, 32>>>(y_mask, out);
}

// round 10
// speedup vs baseline: 1.0806x; 1.0074x over previous
#include <cuda_runtime.h>
#include <cuda_fp16.h>
#include <math.h>
#include <stdint.h>

#define TX 160
#define TY 40
#define BB 16
#define HH 256
#define CC 512
#define INDIM 128
#define VV 30000
#define G4 1024      // 4*H
#define FF 896       // H + C + IN

#define NBLK 128
#define NTHR 320

// ---------------- device scratch (static, no allocs) ----------------
__device__ __align__(256) float g_pctx[TX * BB * CC];          // 5.24 MB
__device__ __align__(256) float g_gates[BB * G4];
__device__ __align__(256) float g_hq[BB * CC];
__device__ __align__(256) float g_acc[BB * TX];
__device__ __align__(256) float g_sc[BB * TX];
__device__ __align__(256) float g_atted[BB * CC];
__device__ __align__(256) float g_ifoc[BB * G4];
__device__ __align__(256) float g_feats[TY * BB * FF];         // 2.29 MB
__device__ __align__(256) float g_logits[TY * BB * VV];        // 76.8 MB
__device__ __align__(256) float g_cost[TY * BB];
__device__ float g_cov_sum;
__device__ __align__(128) unsigned g_bar;
// pre-split tf32 operand buffers (big/small)
__device__ __align__(256) float g_SAb[TX * BB * CC];           // max(context, feats)
__device__ __align__(256) float g_SAs[TX * BB * CC];
__device__ __align__(256) float g_SBb[VV * FF];                // max(Wp, Wc_att) 107.5MB
__device__ __align__(256) float g_SBs[VV * FF];

// ---------------- helpers ----------------
__device__ __forceinline__ float tanh_fast(float x) {
    float y;
    asm("tanh.approx.f32 %0, %1;" : "=f"(y) : "f"(x));
    return y;
}
__device__ __forceinline__ float sig_fast(float x) {
    return fmaf(tanh_fast(0.5f * x), 0.5f, 0.5f);
}
__device__ __forceinline__ float warp_sum(float s) {
#pragma unroll
    for (int o = 16; o > 0; o >>= 1) s += __shfl_xor_sync(0xffffffffu, s, o);
    return s;
}

#define ACC_CHUNK(WPTR, XEXPR) { \
    float4 w = *(const float4*)(WPTR); \
    _Pragma("unroll") \
    for (int b = 0; b < 16; b++) { \
        float4 x = *(const float4*)(XEXPR); \
        acc[b] = fmaf(w.x, x.x, fmaf(w.y, x.y, fmaf(w.z, x.z, fmaf(w.w, x.w, acc[b])))); \
    } }

#define ALLRED16() { \
    _Pragma("unroll") \
    for (int o = 16; o > 0; o >>= 1) { \
        _Pragma("unroll") \
        for (int b = 0; b < 16; b++) acc[b] += __shfl_xor_sync(0xffffffffu, acc[b], o); \
    } }

// fast monotonic grid barrier
__device__ __forceinline__ void grid_sync(unsigned& epoch) {
    __syncthreads();
    if (threadIdx.x == 0) {
        epoch += gridDim.x;
        asm volatile("red.release.gpu.global.add.u32 [%0], 1;" :: "l"(&g_bar) : "memory");
        unsigned v;
        while (true) {
            asm volatile("ld.acquire.gpu.global.u32 %0, [%1];" : "=r"(v) : "l"(&g_bar) : "memory");
            if (v >= epoch) break;
            __nanosleep(32);
        }
    }
    __syncthreads();
}

// ---------------- init ----------------
__global__ void init_kernel(const float* __restrict__ cov0) {
    int tid = threadIdx.x;
    if (tid == 0) { g_bar = 0u; g_cov_sum = 0.f; }
    for (int i = tid; i < BB * TX; i += blockDim.x) { g_acc[i] = cov0[i]; }
}

// ---------------- tf32 split ----------------
__device__ __forceinline__ void split_tf32(float v, float& hi, float& lo) {
    uint32_t bh;
    asm("cvt.rna.tf32.f32 %0, %1;" : "=r"(bh) : "f"(v));
    float fh = __uint_as_float(bh);
    float r = v - fh;
    uint32_t bl;
    asm("cvt.rna.tf32.f32 %0, %1;" : "=r"(bl) : "f"(r));
    hi = fh;
    lo = __uint_as_float(bl);
}

__global__ __launch_bounds__(256) void split_kernel(const float* __restrict__ src,
                                                    float* __restrict__ db,
                                                    float* __restrict__ ds, int n4) {
    int i = blockIdx.x * 256 + threadIdx.x;
    if (i < n4) {
        float4 v = ((const float4*)src)[i];
        float4 hb, lb;
        split_tf32(v.x, hb.x, lb.x);
        split_tf32(v.y, hb.y, lb.y);
        split_tf32(v.z, hb.z, lb.z);
        split_tf32(v.w, hb.w, lb.w);
        ((float4*)db)[i] = hb;
        ((float4*)ds)[i] = lb;
    }
}

// ---------------- 3xTF32 tensor GEMM, cp.async double-buffer, pre-split ----------------
__device__ __forceinline__ void mma_tf32(float* d, const uint32_t* a, const uint32_t* b) {
    asm volatile(
        "mma.sync.aligned.m16n8k8.row.col.f32.tf32.tf32.f32 "
        "{%0,%1,%2,%3}, {%4,%5,%6,%7}, {%8,%9}, {%0,%1,%2,%3};"
        : "+f"(d[0]), "+f"(d[1]), "+f"(d[2]), "+f"(d[3])
        : "r"(a[0]), "r"(a[1]), "r"(a[2]), "r"(a[3]), "r"(b[0]), "r"(b[1]));
}
__device__ __forceinline__ void cp_async16(uint32_t s, const void* g, int sz) {
    asm volatile("cp.async.cg.shared.global [%0], [%1], 16, %2;" :: "r"(s), "l"(g), "r"(sz));
}
#define CP_COMMIT() asm volatile("cp.async.commit_group;")

#define STG 16384
#define GEMM_SMEM (2 * STG * 4)

__global__ __launch_bounds__(256, 1) void gemm_tf32_abT_bias(
    const float* __restrict__ Ab, const float* __restrict__ As,
    const float* __restrict__ Bb, const float* __restrict__ Bs,
    const float* __restrict__ bias, float* __restrict__ Cout,
    int M, int N, int K)
{
    extern __shared__ __align__(16) float sm[];
    const uint32_t smem_base = (uint32_t)__cvta_generic_to_shared(sm);

    const int tid = threadIdx.x;
    const int lane = tid & 31, wid = tid >> 5;
    const int g = lane >> 2, tig = lane & 3;
    const int wm = wid & 3, wn = wid >> 2;
    const int m0 = blockIdx.x * 128, n0 = blockIdx.y * 128;
    const int nt = K >> 5;

    const int s_row[4] = { (tid + 0) >> 3, (tid + 256) >> 3, (tid + 512) >> 3, (tid + 768) >> 3 };
    const int s_k4 = tid & 7;

    float acc[2][8][4];
#pragma unroll
    for (int mt = 0; mt < 2; mt++)
#pragma unroll
        for (int ntt = 0; ntt < 8; ntt++)
#pragma unroll
            for (int r = 0; r < 4; r++) acc[mt][ntt][r] = 0.f;

#define ISSUE_TILE(KT) { \
    int k0 = (KT) * 32; \
    uint32_t base = smem_base + ((KT) & 1) * (STG * 4); \
    _Pragma("unroll") \
    for (int i = 0; i < 4; i++) { \
        int row = s_row[i]; \
        uint32_t wb_ = (uint32_t)(row * 32 + ((s_k4 * 4) ^ ((row & 7) << 2))) * 4; \
        size_t offA = (size_t)(m0 + row) * K + k0 + s_k4 * 4; \
        cp_async16(base + wb_, Ab + offA, 16); \
        cp_async16(base + 4096 * 4 + wb_, As + offA, 16); \
        int gn = n0 + row; \
        int sz = (gn < N) ? 16 : 0; \
        size_t offB = (size_t)(gn < N ? gn : 0) * K + k0 + s_k4 * 4; \
        cp_async16(base + 8192 * 4 + wb_, Bb + offB, sz); \
        cp_async16(base + 12288 * 4 + wb_, Bs + offB, sz); \
    } \
    CP_COMMIT(); }

    ISSUE_TILE(0);

    for (int kt = 0; kt < nt; kt++) {
        if (kt + 1 < nt) {
            ISSUE_TILE(kt + 1);
            asm volatile("cp.async.wait_group 1;");
        } else {
            asm volatile("cp.async.wait_group 0;");
        }
        __syncthreads();

        const float* sAb = sm + (kt & 1) * STG;
        const float* sAs = sAb + 4096;
        const float* sBb = sAb + 8192;
        const float* sBs = sAb + 12288;
#pragma unroll
        for (int k8 = 0; k8 < 4; k8++) {
            const int kb = k8 * 8;
            uint32_t ab[2][4], as_[2][4];
#pragma unroll
            for (int mt = 0; mt < 2; mt++) {
                int r0 = wm * 32 + mt * 16 + g;
                int sw = (r0 & 7) << 2;
                int i0 = r0 * 32 + ((kb + tig) ^ sw);
                int i1 = r0 * 32 + ((kb + tig + 4) ^ sw);
                ab[mt][0] = __float_as_uint(sAb[i0]);
                ab[mt][1] = __float_as_uint(sAb[i0 + 256]);
                ab[mt][2] = __float_as_uint(sAb[i1]);
                ab[mt][3] = __float_as_uint(sAb[i1 + 256]);
                as_[mt][0] = __float_as_uint(sAs[i0]);
                as_[mt][1] = __float_as_uint(sAs[i0 + 256]);
                as_[mt][2] = __float_as_uint(sAs[i1]);
                as_[mt][3] = __float_as_uint(sAs[i1 + 256]);
            }
            uint32_t bb[8][2], bs[8][2];
#pragma unroll
            for (int ntt = 0; ntt < 8; ntt++) {
                int c0 = wn * 64 + ntt * 8 + g;
                int sw = (c0 & 7) << 2;
                int j0 = c0 * 32 + ((kb + tig) ^ sw);
                int j1 = c0 * 32 + ((kb + tig + 4) ^ sw);
                bb[ntt][0] = __float_as_uint(sBb[j0]);
                bb[ntt][1] = __float_as_uint(sBb[j1]);
                bs[ntt][0] = __float_as_uint(sBs[j0]);
                bs[ntt][1] = __float_as_uint(sBs[j1]);
            }
#pragma unroll
            for (int mt = 0; mt < 2; mt++)
#pragma unroll
                for (int ntt = 0; ntt < 8; ntt++) {
                    mma_tf32(acc[mt][ntt], ab[mt], bb[ntt]);
                    mma_tf32(acc[mt][ntt], ab[mt], bs[ntt]);
                    mma_tf32(acc[mt][ntt], as_[mt], bb[ntt]);
                }
        }
        __syncthreads();
    }
#undef ISSUE_TILE

    // epilogue
#pragma unroll
    for (int mt = 0; mt < 2; mt++) {
        int r0 = m0 + wm * 32 + mt * 16 + g;
#pragma unroll
        for (int ntt = 0; ntt < 8; ntt++) {
            int c = n0 + wn * 64 + ntt * 8 + tig * 2;
            if (c + 1 < N) {
                float2 v0 = make_float2(acc[mt][ntt][0] + bias[c], acc[mt][ntt][1] + bias[c + 1]);
                float2 v1 = make_float2(acc[mt][ntt][2] + bias[c], acc[mt][ntt][3] + bias[c + 1]);
                *(float2*)&Cout[(size_t)r0 * N + c] = v0;
                *(float2*)&Cout[(size_t)(r0 + 8) * N + c] = v1;
            } else if (c < N) {
                Cout[(size_t)r0 * N + c] = acc[mt][ntt][0] + bias[c];
                Cout[(size_t)(r0 + 8) * N + c] = acc[mt][ntt][2] + bias[c];
            }
        }
    }
}

// ---------------- persistent recurrence ----------------
#define OFF_H    0
#define OFF_C    4096
#define OFF_H1   8192
#define OFF_C1   12288
#define OFF_WATT 16384
#define OFF_ATTP 16544
#define OFF_WCOV 16864
#define OFF_UATT 17376
#define SMEM_FLOATS 17888
#define SMEM_BYTES (SMEM_FLOATS * 4)

__global__ __launch_bounds__(NTHR, 1) void decoder_kernel(
    const float* __restrict__ y_emb, const float* __restrict__ context,
    const float* __restrict__ x_mask, const float* __restrict__ y_mask,
    const float* __restrict__ h0, const float* __restrict__ c0,
    const float* __restrict__ W_ih, const float* __restrict__ W_hh,
    const float* __restrict__ b_ih, const float* __restrict__ b_hh,
    const float* __restrict__ Wx, const float* __restrict__ Ux, const float* __restrict__ bx,
    const float* __restrict__ W_comb, const float* __restrict__ U_att,
    const float* __restrict__ W_cov)
{
    extern __shared__ __align__(16) float sh[];
    float* sh_h    = sh + OFF_H;
    float* sh_c    = sh + OFF_C;
    float* sh_h1   = sh + OFF_H1;
    float* sh_c1   = sh + OFF_C1;
    float* sh_watt = sh + OFF_WATT;
    float* sh_attp = sh + OFF_ATTP;
    float* sh_wcov = sh + OFF_WCOV;
    float* sh_uatt = sh + OFF_UATT;

    const int tid = threadIdx.x;
    const int bk = blockIdx.x;
    const int lane = tid & 31;
    const int lwid = tid >> 5;
    const int myb = bk >> 3;
    const int sub = bk & 7;
    unsigned epoch = 0;

    for (int i = tid; i < BB * HH; i += NTHR) { sh_h[i] = h0[i]; sh_c[i] = c0[i]; }
    for (int i = tid; i < CC; i += NTHR) { sh_wcov[i] = W_cov[i]; sh_uatt[i] = U_att[i]; }
    __syncthreads();

    for (int t = 0; t < TY; t++) {
        const float* yrow = y_emb + (size_t)t * BB * INDIM;

        // P1
        if (lwid < 8) {
            int j = lwid * NBLK + bk;
            float acc[16];
#pragma unroll
            for (int b = 0; b < 16; b++) acc[b] = 0.f;
            ACC_CHUNK(W_ih + (size_t)j * INDIM + lane * 4,     yrow + b * INDIM + lane * 4);
            ACC_CHUNK(W_hh + (size_t)j * HH + lane * 4,        sh_h + b * HH + lane * 4);
            ACC_CHUNK(W_hh + (size_t)j * HH + 128 + lane * 4,  sh_h + b * HH + 128 + lane * 4);
            ALLRED16();
            float bias = b_ih[j] + b_hh[j];
#pragma unroll
            for (int b = 0; b < 16; b++)
                if (lane == b) g_gates[b * G4 + j] = acc[b] + bias;
        }
        grid_sync(epoch);

        // P2
        for (int idx = tid; idx < BB * HH; idx += NTHR) {
            int b = idx >> 8, u = idx & 255;
            const float* gb = g_gates + b * G4 + u;
            float gi = gb[0], gf = gb[HH], gg = gb[2 * HH], go = gb[3 * HH];
            float c_old = sh_c[idx], h_old = sh_h[idx];
            float c1 = sig_fast(gf) * c_old + sig_fast(gi) * tanh_fast(gg);
            float h1 = sig_fast(go) * tanh_fast(c1);
            float ym = y_mask[t * BB + b];
            sh_h1[idx] = ym * h1 + (1.f - ym) * h_old;
            sh_c1[idx] = ym * c1 + (1.f - ym) * c_old;
        }
        __syncthreads();

        // P3
        if (lwid < 4) {
            int o = lwid * NBLK + bk;
            const float* wr = W_comb + (size_t)o * (2 * HH);
            float acc[16];
#pragma unroll
            for (int b = 0; b < 16; b++) acc[b] = 0.f;
            ACC_CHUNK(wr + lane * 4,        sh_h1 + b * HH + lane * 4);
            ACC_CHUNK(wr + 128 + lane * 4,  sh_h1 + b * HH + 128 + lane * 4);
            ACC_CHUNK(wr + 256 + lane * 4,  sh_c1 + b * HH + lane * 4);
            ACC_CHUNK(wr + 384 + lane * 4,  sh_c1 + b * HH + 128 + lane * 4);
            ALLRED16();
#pragma unroll
            for (int b = 0; b < 16; b++)
                if (lane == b) g_hq[b * CC + o] = acc[b];
        }
        grid_sync(epoch);

        // P4: f16x2 tanh (2 channels per MUFU op)
#pragma unroll
        for (int r = 0; r < 2; r++) {
            int p = (r * 10 + lwid) * NBLK + bk;
            int x = p >> 4, b = p & 15;
            float accv = g_acc[b * TX + x];
            const float* pc = g_pctx + (size_t)p * CC;
            const float* hqb = g_hq + b * CC;
            float s = 0.f;
#pragma unroll
            for (int i = 0; i < 8; i++) {
                int c  = i * 32 + lane;
                int c2 = c + 256;
                float a1 = fmaf(accv, sh_wcov[c],  pc[c]  + hqb[c]);
                float a2 = fmaf(accv, sh_wcov[c2], pc[c2] + hqb[c2]);
                __half2 hp = __floats2half2_rn(a1, a2);
                uint32_t hu = *(uint32_t*)&hp;
                uint32_t tr;
                asm("tanh.approx.f16x2 %0, %1;" : "=r"(tr) : "r"(hu));
                __half2 th = *(__half2*)&tr;
                float2 tf = __half22float2(th);
                s = fmaf(tf.x, sh_uatt[c], fmaf(tf.y, sh_uatt[c2], s));
            }
            s = warp_sum(s);
            if (lane == 0) g_sc[b * TX + x] = x_mask[p] * s;
        }
        grid_sync(epoch);

        // P5a
        if (lwid == 0) {
            float v[5];
            float mx = -3.4e38f;
#pragma unroll
            for (int i = 0; i < 5; i++) {
                v[i] = g_sc[myb * TX + i * 32 + lane];
                mx = fmaxf(mx, v[i]);
            }
#pragma unroll
            for (int o = 16; o > 0; o >>= 1) mx = fmaxf(mx, __shfl_xor_sync(0xffffffffu, mx, o));
            float sm = 0.f;
#pragma unroll
            for (int i = 0; i < 5; i++) {
                v[i] = __expf(v[i] - mx) * x_mask[(i * 32 + lane) * BB + myb];
                sm += v[i];
            }
            sm = warp_sum(sm);
            float inv = __fdividef(1.f, sm);
#pragma unroll
            for (int i = 0; i < 5; i++) sh_watt[i * 32 + lane] = v[i] * inv;
        }
        __syncthreads();

        // P5b
        {
            int jid = sub * 10 + lwid;
            int cck = jid / 5, xck = jid % 5;
            int c = cck * 32 + lane;
            float s = 0.f;
#pragma unroll 8
            for (int i = 0; i < 32; i++) {
                int x = xck * 32 + i;
                s = fmaf(sh_watt[x], context[(size_t)(x * BB + myb) * CC + c], s);
            }
            sh_attp[(cck & 1) * 160 + xck * 32 + lane] = s;
        }
        __syncthreads();
        if (tid < 64) {
            int lc = tid >> 5, cl = tid & 31;
            const float* ap = sh_attp + lc * 160 + cl;
            float s = ap[0] + ap[32] + ap[64] + ap[96] + ap[128];
            g_atted[myb * CC + (2 * sub + lc) * 32 + cl] = s;
        }
        if (sub == 0 && lwid == 2) {
            float part = 0.f;
#pragma unroll
            for (int i = 0; i < 5; i++) {
                int x = i * 32 + lane;
                float w = sh_watt[x];
                float old = g_acc[myb * TX + x];
                part += fminf(w, old);
                g_acc[myb * TX + x] = old + w;
            }
            part = warp_sum(part);
            if (lane == 0) atomicAdd(&g_cov_sum, part);
        }
        grid_sync(epoch);

        // P6
        if (lwid < 8) {
            int j = lwid * NBLK + bk;
            float acc[16];
#pragma unroll
            for (int b = 0; b < 16; b++) acc[b] = 0.f;
            ACC_CHUNK(Ux + (size_t)j * HH + lane * 4,        sh_h1 + b * HH + lane * 4);
            ACC_CHUNK(Ux + (size_t)j * HH + 128 + lane * 4,  sh_h1 + b * HH + 128 + lane * 4);
#pragma unroll
            for (int cc = 0; cc < 4; cc++) {
                ACC_CHUNK(Wx + (size_t)j * CC + cc * 128 + lane * 4,
                          g_atted + b * CC + cc * 128 + lane * 4);
            }
            ALLRED16();
            float bias = bx[j];
#pragma unroll
            for (int b = 0; b < 16; b++)
                if (lane == b) g_ifoc[b * G4 + j] = acc[b] + bias;
        }
        grid_sync(epoch);

        // P7
        for (int idx = tid; idx < BB * HH; idx += NTHR) {
            int b = idx >> 8, u = idx & 255;
            const float* fb = g_ifoc + b * G4 + u;
            float i2 = fb[0], f2 = fb[HH], o2 = fb[2 * HH], g2 = fb[3 * HH];
            float c1 = sh_c1[idx], h1 = sh_h1[idx];
            float c2 = sig_fast(f2) * c1 + sig_fast(i2) * tanh_fast(g2);
            float h2 = sig_fast(o2) * tanh_fast(c2);
            float ym = y_mask[t * BB + b];
            c2 = ym * c2 + (1.f - ym) * c1;
            h2 = ym * h2 + (1.f - ym) * h1;
            sh_h[idx] = h2;
            sh_c[idx] = c2;
            g_feats[(size_t)(t * BB + b) * FF + u] = h2;
        }
        for (int idx2 = bk * NTHR + tid; idx2 < BB * (CC + INDIM); idx2 += NBLK * NTHR) {
            if (idx2 < BB * CC) {
                int b = idx2 >> 9, c = idx2 & 511;
                g_feats[(size_t)(t * BB + b) * FF + HH + c] = g_atted[idx2];
            } else {
                int q = idx2 - BB * CC;
                int b = q >> 7, kk = q & 127;
                g_feats[(size_t)(t * BB + b) * FF + HH + CC + kk] = yrow[b * INDIM + kk];
            }
        }
        __syncthreads();
    }
}

// ---------------- online softmax / cost per row ----------------
__global__ __launch_bounds__(256) void softmax_cost_kernel(const int* __restrict__ y_idx,
                                                           float* __restrict__ out) {
    __shared__ float smx[256], ssm[256];
    const int m = blockIdx.x;
    const int tid = threadIdx.x;
    const float* row = g_logits + (size_t)m * VV;

    float mx = -3.4e38f, sm = 0.f;
    for (int v = tid; v < VV; v += 256) {
        float x = row[v];
        float nm = fmaxf(mx, x);
        sm = sm * __expf(mx - nm) + __expf(x - nm);
        mx = nm;
    }
    smx[tid] = mx; ssm[tid] = sm; __syncthreads();
    for (int s = 128; s > 0; s >>= 1) {
        if (tid < s) {
            float m2 = smx[tid + s], s2 = ssm[tid + s];
            float nm = fmaxf(smx[tid], m2);
            ssm[tid] = ssm[tid] * __expf(smx[tid] - nm) + s2 * __expf(m2 - nm);
            smx[tid] = nm;
        }
        __syncthreads();
    }
    float M = smx[0], S = ssm[0];
    if (tid == 0) g_cost[m] = M + logf(S) - row[y_idx[m]];

    if (m >= (TY - 1) * BB) {
        int b = m - (TY - 1) * BB;
        float inv = __fdividef(1.f, S);
        for (int v = tid; v < VV; v += 256)
            out[(size_t)b * VV + v] = __expf(row[v] - M) * inv;
    }
}

// ---------------- final scalars ----------------
__global__ void finalize_kernel(const float* __restrict__ y_mask, float* __restrict__ out) {
    int b = threadIdx.x;
    float cb = 0.f;
    if (b < BB) {
        float num = 0.f, den = 0.f;
        for (int t = 0; t < TY; t++) {
            float ym = y_mask[t * BB + b];
            num += g_cost[t * BB + b] * ym;
            den += ym;
        }
        cb = num / den;
    }
#pragma unroll
    for (int o = 16; o > 0; o >>= 1) cb += __shfl_xor_sync(0xffffffffu, cb, o);
    if (threadIdx.x == 0) {
        out[(size_t)BB * VV]     = cb / (float)BB;
        out[(size_t)BB * VV + 1] = g_cov_sum / (float)(TY * BB);
    }
}

// ---------------- launch ----------------
extern "C" void kernel_launch(void* const* d_in, const int* in_sizes, int n_in,
                              void* d_out, int out_size) {
    const float* y_emb   = (const float*)d_in[0];
    const float* context = (const float*)d_in[1];
    const float* h0      = (const float*)d_in[2];
    const float* c0      = (const float*)d_in[3];
    const float* x_mask  = (const float*)d_in[4];
    const float* y_mask  = (const float*)d_in[5];
    const float* cov0    = (const float*)d_in[6];
    const int*   y_idx   = (const int*)d_in[7];
    const float* W_ih    = (const float*)d_in[8];
    const float* W_hh    = (const float*)d_in[9];
    const float* b_ih    = (const float*)d_in[10];
    const float* b_hh    = (const float*)d_in[11];
    const float* Wx      = (const float*)d_in[12];
    const float* Ux      = (const float*)d_in[13];
    const float* bx      = (const float*)d_in[14];
    const float* Wc_att  = (const float*)d_in[15];
    const float* b_att   = (const float*)d_in[16];
    const float* W_comb  = (const float*)d_in[17];
    const float* U_att   = (const float*)d_in[18];
    const float* W_cov   = (const float*)d_in[19];
    const float* Wp      = (const float*)d_in[20];
    const float* bp      = (const float*)d_in[21];
    float* out = (float*)d_out;

    void *p_pctx, *p_feats, *p_logits, *p_ab, *p_as, *p_bb, *p_bs;
    cudaGetSymbolAddress(&p_pctx, g_pctx);
    cudaGetSymbolAddress(&p_feats, g_feats);
    cudaGetSymbolAddress(&p_logits, g_logits);
    cudaGetSymbolAddress(&p_ab, g_SAb);
    cudaGetSymbolAddress(&p_as, g_SAs);
    cudaGetSymbolAddress(&p_bb, g_SBb);
    cudaGetSymbolAddress(&p_bs, g_SBs);

    cudaFuncSetAttribute(decoder_kernel,
                         cudaFuncAttributeMaxDynamicSharedMemorySize, SMEM_BYTES);
    cudaFuncSetAttribute(gemm_tf32_abT_bias,
                         cudaFuncAttributeMaxDynamicSharedMemorySize, GEMM_SMEM);

    init_kernel<<<1, 256>>>(cov0);

    // pctx = context @ Wc_att^T + b_att
    {
        int nA = (TX * BB * CC) / 4, nB = (CC * CC) / 4;
        split_kernel<<<(nA + 255) / 256, 256>>>(context, (float*)p_ab, (float*)p_as, nA);
        split_kernel<<<(nB + 255) / 256, 256>>>(Wc_att, (float*)p_bb, (float*)p_bs, nB);
        dim3 grid((TX * BB) / 128, CC / 128);   // (20, 4)
        gemm_tf32_abT_bias<<<grid, 256, GEMM_SMEM>>>((const float*)p_ab, (const float*)p_as,
                                                     (const float*)p_bb, (const float*)p_bs,
                                                     b_att, (float*)p_pctx, TX * BB, CC, CC);
    }

    decoder_kernel<<<NBLK, NTHR, SMEM_BYTES>>>(y_emb, context, x_mask, y_mask,
                                               h0, c0,
                                               W_ih, W_hh, b_ih, b_hh, Wx, Ux, bx,
                                               W_comb, U_att, W_cov);

    // logits = feats @ Wp^T + bp
    {
        int nA = (TY * BB * FF) / 4, nB = (VV * FF) / 4;
        split_kernel<<<(nA + 255) / 256, 256>>>((const float*)p_feats, (float*)p_ab, (float*)p_as, nA);
        split_kernel<<<(nB + 255) / 256, 256>>>(Wp, (float*)p_bb, (float*)p_bs, nB);
        dim3 grid((TY * BB) / 128, (VV + 127) / 128);   // (5, 235)
        gemm_tf32_abT_bias<<<grid, 256, GEMM_SMEM>>>((const float*)p_ab, (const float*)p_as,
                                                     (const float*)p_bb, (const float*)p_bs,
                                                     bp, (float*)p_logits, TY * BB, VV, FF);
    }

    softmax_cost_kernel<<<TY * BB, 256>>>(y_idx, out);
    finalize_kernel<<<1, 32>>>(y_mask, out);
}